// round 3
// baseline (speedup 1.0000x reference)
#include <cuda_runtime.h>
#include <cstdint>

// ItemEncoder: out[t,:] = M[ids[t],:] @ W^T + b ; 12800 tokens, D=2000, O=8.
//
// R3 design (GB300 / sm_103a):
//  - 1 CTA / SM, 256 threads (8 warps).
//  - W held in REGISTERS: warp w owns quads [w*64, w*64+64); per lane
//    2 iters x 8 outputs x 16B = 64 regs. Loaded once via LDG (L2 broadcast).
//  - Rows gathered in 4-token stages (32 KB) via cp.async.cg into a 6-deep
//    smem ring; prefetch depth 5 (up to 160 KB in flight per SM).
//  - All 8 warps compute the same 4 tokens (each its quad slice), packed
//    fp32x2 FMAs, butterfly transpose-reduce, cross-warp sum in smem,
//    one coalesced 128B store per stage.

static constexpr int NTOK  = 12800;
static constexpr int D     = 2000;
static constexpr int ROWB  = D * 4;        // 8000 B / row
static constexpr int QPR   = D / 4;        // 500 quads / row
static constexpr int STOK  = 4;            // tokens per stage
static constexpr int NSTG  = NTOK / STOK;  // 3200 stages
static constexpr int SQ    = STOK * QPR;   // 2000 quads / stage
static constexpr int NTHR  = 256;

static constexpr int NBUF  = 6;
static constexpr int BSTRIDE = 32256;      // 4*8000 data + 256 zeroed pad
static constexpr int SM_RED  = NBUF * BSTRIDE;          // 193536
static constexpr int SM_TOT  = SM_RED + 8 * 32 * 4;     // +1024 = 194560

__device__ __forceinline__ void ffma2(unsigned long long &acc,
                                      unsigned long long a,
                                      unsigned long long b) {
    asm("fma.rn.f32x2 %0, %1, %2, %0;" : "+l"(acc) : "l"(a), "l"(b));
}

__device__ __forceinline__ void cp16(void* smem_dst, const void* gmem_src) {
    unsigned s = (unsigned)__cvta_generic_to_shared(smem_dst);
    asm volatile("cp.async.cg.shared.global [%0], [%1], 16;\n"
                 :: "r"(s), "l"(gmem_src));
}
__device__ __forceinline__ void cp_commit() {
    asm volatile("cp.async.commit_group;\n" ::: "memory");
}
__device__ __forceinline__ void cp_wait4() {
    asm volatile("cp.async.wait_group 4;\n" ::: "memory");
}

// Gather one 4-token stage into dst (2000 x 16B cp.async ops).
__device__ __forceinline__ void issue_stage(char* dst, const int* __restrict__ ids,
                                            const char* __restrict__ Mb,
                                            int stage, int tid) {
#pragma unroll
    for (int k = 0; k < 8; ++k) {
        int j = tid + k * NTHR;
        if (j < SQ) {
            int r = (int)(((unsigned long long)(unsigned)j * 8389ull) >> 22); // j/500
            int c = j - r * 500;
            int row = __ldg(ids + stage * STOK + r);
            cp16(dst + r * ROWB + c * 16,
                 Mb + (size_t)row * ROWB + (size_t)c * 16);
        }
    }
}

__global__ void __launch_bounds__(NTHR, 1)
gather_proj_r3(const int*   __restrict__ ids,
               const float* __restrict__ M,
               const float* __restrict__ W,
               const float* __restrict__ bias,
               float*       __restrict__ out)
{
    extern __shared__ char smem[];
    const int tid  = threadIdx.x;
    const int lane = tid & 31;
    const int wid  = tid >> 5;

    const char* Mb = (const char*)M;
    const float bval = __ldg(bias + (lane & 7));

    // ---- zero the per-buffer padding (quads 500..511 land there) ----
    if (tid < NBUF * 16) {
        int b = tid >> 4, q = tid & 15;
        *(float4*)(smem + b * BSTRIDE + STOK * ROWB + q * 16) =
            make_float4(0.f, 0.f, 0.f, 0.f);
    }

    // ---- W into registers: this warp's quads q = wid*64 + it*32 + lane ----
    ulonglong2 w[2][8];
#pragma unroll
    for (int it = 0; it < 2; ++it) {
        const int q = wid * 64 + it * 32 + lane;
#pragma unroll
        for (int o = 0; o < 8; ++o) {
            if (q < QPR) w[it][o] = __ldg((const ulonglong2*)W + o * QPR + q);
            else         w[it][o] = make_ulonglong2(0ull, 0ull);
        }
    }

    const int grid   = gridDim.x;
    const int s0     = blockIdx.x;
    const int nLocal = (NSTG - s0 + grid - 1) / grid;

    // ---- prologue: fill pipeline depth 5 ----
#pragma unroll
    for (int p = 0; p < NBUF - 1; ++p) {
        if (p < nLocal)
            issue_stage(smem + p * BSTRIDE, ids, Mb, s0 + p * grid, tid);
        cp_commit();
    }

    float* red = (float*)(smem + SM_RED);

    for (int k = 0; k < nLocal; ++k) {
        cp_wait4();            // stage k complete (<=4 newer groups outstanding)
        __syncthreads();       // (A) stage k visible; red[] readers of k-1 done

        // prefetch stage k+5 into the ring slot freed by compute k-1
        if (k + NBUF - 1 < nLocal)
            issue_stage(smem + ((k + NBUF - 1) % NBUF) * BSTRIDE, ids, Mb,
                        s0 + (k + NBUF - 1) * grid, tid);
        cp_commit();

        const char* buf = smem + (k % NBUF) * BSTRIDE;

        unsigned long long acc[4][8];
#pragma unroll
        for (int t = 0; t < 4; ++t)
#pragma unroll
            for (int o = 0; o < 8; ++o) acc[t][o] = 0ull;

#pragma unroll
        for (int it = 0; it < 2; ++it) {
            const int q = wid * 64 + it * 32 + lane;   // may be >=500: pad reads, w=0
            ulonglong2 v[4];
#pragma unroll
            for (int t = 0; t < 4; ++t)
                v[t] = *(const ulonglong2*)(buf + t * ROWB + q * 16);
#pragma unroll
            for (int t = 0; t < 4; ++t)
#pragma unroll
                for (int o = 0; o < 8; ++o) {
                    ffma2(acc[t][o], v[t].x, w[it][o].x);
                    ffma2(acc[t][o], v[t].y, w[it][o].y);
                }
        }

        // collapse f32x2 halves -> 32 scalars, butterfly transpose-reduce
        float cur[32];
#pragma unroll
        for (int t = 0; t < 4; ++t)
#pragma unroll
            for (int o = 0; o < 8; ++o) {
                const unsigned long long a = acc[t][o];
                cur[t * 8 + o] = __uint_as_float((unsigned)a) +
                                 __uint_as_float((unsigned)(a >> 32));
            }
#pragma unroll
        for (int off = 16; off >= 1; off >>= 1) {
            const bool up = (lane & off) != 0;
#pragma unroll
            for (int j = 0; j < off; ++j) {
                float keep = up ? cur[j + off] : cur[j];
                float give = up ? cur[j] : cur[j + off];
                keep += __shfl_xor_sync(0xffffffffu, give, off);
                cur[j] = keep;
            }
        }
        // lane holds partial of output value index `lane` (token lane>>3, out lane&7)
        red[wid * 32 + lane] = cur[0];
        __syncthreads();       // (B) red visible; all warps done with buf

        if (wid == 0) {
            float s = bval;
#pragma unroll
            for (int ww = 0; ww < 8; ++ww) s += red[ww * 32 + lane];
            out[(size_t)(s0 + k * grid) * 32 + lane] = s;
        }
    }
}

extern "C" void kernel_launch(void* const* d_in, const int* in_sizes, int n_in,
                              void* d_out, int out_size) {
    const int*   ids  = (const int*)  d_in[0];
    const float* M    = (const float*)d_in[1];
    const float* W    = (const float*)d_in[2];
    const float* bias = (const float*)d_in[3];
    float*       out  = (float*)d_out;

    cudaFuncSetAttribute(gather_proj_r3,
                         cudaFuncAttributeMaxDynamicSharedMemorySize, SM_TOT);

    int nsm = 148;
    cudaDeviceGetAttribute(&nsm, cudaDevAttrMultiProcessorCount, 0);

    gather_proj_r3<<<nsm, NTHR, SM_TOT>>>(ids, M, W, bias, out);
}

// round 5
// speedup vs baseline: 2.1502x; 2.1502x over previous
#include <cuda_runtime.h>
#include <cstdint>

// ItemEncoder R4: warp-specialized TMA-bulk gather pipeline.
//   out[t,:] = M[ids[t],:] @ W^T + b ; 12800 tokens, D=2000, O=8.
//
//  - 1 CTA / SM, 288 threads: warps 0-7 consumers, warp 8 producer.
//  - Producer lane 0: per stage (4 tokens) waits empty[slot], arms
//    full[slot] with expect_tx(32000), issues 4x cp.async.bulk (8000 B
//    contiguous row each). Bulk path bypasses the per-SM LSU/L1tex
//    request queue that capped rounds 1-3 at ~3 TB/s.
//  - 6-slot smem ring: up to ~160 KB in flight per SM at all times.
//  - Consumers: W in registers (warp w owns quads [w*64,w*64+64)),
//    packed fp32x2 FMAs, butterfly transpose-reduce, cross-warp sum via
//    smem `red`, coalesced 128 B store. Named barrier (id 1, 256 thr)
//    so the producer warp is never coupled.

static constexpr int NTOK  = 12800;
static constexpr int D     = 2000;
static constexpr int ROWB  = D * 4;          // 8000 B
static constexpr int QPR   = D / 4;          // 500
static constexpr int STOK  = 4;
static constexpr int NSTG  = NTOK / STOK;    // 3200
static constexpr int NTHR  = 288;
static constexpr int NCONS = 256;
static constexpr int NBUF  = 6;
static constexpr int STAGEB  = STOK * ROWB;  // 32000
static constexpr int BSTRIDE = 32256;        // 32000 data + 256 zeroed pad
static constexpr int SM_RED  = NBUF * BSTRIDE;      // 193536
static constexpr int SM_MBAR = SM_RED + 1024;       // 12 mbarriers (16 B/slot)
static constexpr int SM_TOT  = SM_MBAR + NBUF * 16;

__device__ __forceinline__ void ffma2(unsigned long long &acc,
                                      unsigned long long a,
                                      unsigned long long b) {
    asm("fma.rn.f32x2 %0, %1, %2, %0;" : "+l"(acc) : "l"(a), "l"(b));
}

__device__ __forceinline__ void mbar_init(uint32_t a, uint32_t cnt) {
    asm volatile("mbarrier.init.shared.b64 [%0], %1;" :: "r"(a), "r"(cnt) : "memory");
}
__device__ __forceinline__ void mbar_expect_tx(uint32_t a, uint32_t bytes) {
    asm volatile("mbarrier.arrive.expect_tx.shared.b64 _, [%0], %1;"
                 :: "r"(a), "r"(bytes) : "memory");
}
__device__ __forceinline__ void mbar_arrive(uint32_t a) {
    asm volatile("mbarrier.arrive.shared.b64 _, [%0];" :: "r"(a) : "memory");
}
__device__ __forceinline__ void mbar_wait(uint32_t a, uint32_t parity) {
    asm volatile(
        "{\n\t.reg .pred P;\n\t"
        "WL_%=:\n\t"
        "mbarrier.try_wait.parity.acquire.cta.shared::cta.b64 P, [%0], %1, 0x989680;\n\t"
        "@P bra WD_%=;\n\t"
        "bra WL_%=;\n\t"
        "WD_%=:\n\t}"
        :: "r"(a), "r"(parity) : "memory");
}
__device__ __forceinline__ void bulk_cp(uint32_t smem_dst, const void* gmem_src,
                                        uint32_t bytes, uint32_t mbar) {
    asm volatile(
        "cp.async.bulk.shared::cta.global.mbarrier::complete_tx::bytes "
        "[%0], [%1], %2, [%3];"
        :: "r"(smem_dst), "l"(gmem_src), "r"(bytes), "r"(mbar) : "memory");
}
__device__ __forceinline__ void bar_cons() {     // consumers only (256 threads)
    asm volatile("bar.sync 1, %0;" :: "n"(NCONS) : "memory");
}

__global__ void __launch_bounds__(NTHR, 1)
gather_proj_r4(const int*   __restrict__ ids,
               const float* __restrict__ M,
               const float* __restrict__ W,
               const float* __restrict__ bias,
               float*       __restrict__ out)
{
    extern __shared__ char smem[];
    const uint32_t smem_u32 = (uint32_t)__cvta_generic_to_shared(smem);
    const int tid  = threadIdx.x;
    const int lane = tid & 31;
    const int wid  = tid >> 5;

    const int grid   = gridDim.x;
    const int s0     = blockIdx.x;
    const int nLocal = (NSTG - s0 + grid - 1) / grid;

    auto fullb  = [&](int s) -> uint32_t { return smem_u32 + SM_MBAR + s * 16; };
    auto emptyb = [&](int s) -> uint32_t { return smem_u32 + SM_MBAR + s * 16 + 8; };

    // ---- init: mbarriers, zero ring pads ----
    if (tid == 0) {
#pragma unroll
        for (int s = 0; s < NBUF; ++s) {
            mbar_init(fullb(s), 1);        // producer's expect_tx arrive
            mbar_init(emptyb(s), NCONS);   // every consumer thread arrives
        }
    }
    if (tid < NBUF * 16) {                 // 6 x 256 B pad (quads 500..511)
        int b = tid >> 4, q = tid & 15;
        *(float4*)(smem + b * BSTRIDE + STAGEB + q * 16) =
            make_float4(0.f, 0.f, 0.f, 0.f);
    }
    __syncthreads();

    if (wid == 8) {
        // ================= producer =================
        if (lane == 0) {
            const char* Mb = (const char*)M;
            int phase = 1;                 // first empty-wait passes immediately
            for (int k = 0; k < nLocal; ++k) {
                const int slot = k % NBUF;
                mbar_wait(emptyb(slot), phase);
                const int4 ii = __ldg((const int4*)ids + (s0 + k * grid));
                const uint32_t dst = smem_u32 + slot * BSTRIDE;
                mbar_expect_tx(fullb(slot), STAGEB);
                bulk_cp(dst,            Mb + (size_t)ii.x * ROWB, ROWB, fullb(slot));
                bulk_cp(dst + ROWB,     Mb + (size_t)ii.y * ROWB, ROWB, fullb(slot));
                bulk_cp(dst + 2 * ROWB, Mb + (size_t)ii.z * ROWB, ROWB, fullb(slot));
                bulk_cp(dst + 3 * ROWB, Mb + (size_t)ii.w * ROWB, ROWB, fullb(slot));
                if (slot == NBUF - 1) phase ^= 1;
            }
        }
        return;   // lanes 1-31 of warp 8 idle out
    }

    // ================= consumers (warps 0-7) =================
    const float bval = __ldg(bias + (lane & 7));

    // W into registers: this warp's quads q = wid*64 + it*32 + lane
    ulonglong2 w[2][8];
#pragma unroll
    for (int it = 0; it < 2; ++it) {
        const int q = wid * 64 + it * 32 + lane;
#pragma unroll
        for (int o = 0; o < 8; ++o) {
            if (q < QPR) w[it][o] = __ldg((const ulonglong2*)W + o * QPR + q);
            else         w[it][o] = make_ulonglong2(0ull, 0ull);
        }
    }

    float* red = (float*)(smem + SM_RED);
    int phase = 0;

    for (int k = 0; k < nLocal; ++k) {
        const int slot = k % NBUF;
        mbar_wait(fullb(slot), phase);               // stage data visible
        const char* buf = smem + slot * BSTRIDE;

        unsigned long long acc[4][8];
#pragma unroll
        for (int t = 0; t < 4; ++t)
#pragma unroll
            for (int o = 0; o < 8; ++o) acc[t][o] = 0ull;

#pragma unroll
        for (int it = 0; it < 2; ++it) {
            const int q = wid * 64 + it * 32 + lane;  // may be >=500: pad, w=0
            ulonglong2 v[4];
#pragma unroll
            for (int t = 0; t < 4; ++t)
                v[t] = *(const ulonglong2*)(buf + t * ROWB + q * 16);
#pragma unroll
            for (int t = 0; t < 4; ++t)
#pragma unroll
                for (int o = 0; o < 8; ++o) {
                    ffma2(acc[t][o], v[t].x, w[it][o].x);
                    ffma2(acc[t][o], v[t].y, w[it][o].y);
                }
        }
        mbar_arrive(emptyb(slot));     // done reading buf (release)
        if (slot == NBUF - 1) phase ^= 1;

        // collapse f32x2 halves -> 32 scalars, butterfly transpose-reduce
        float cur[32];
#pragma unroll
        for (int t = 0; t < 4; ++t)
#pragma unroll
            for (int o = 0; o < 8; ++o) {
                const unsigned long long a = acc[t][o];
                cur[t * 8 + o] = __uint_as_float((unsigned)a) +
                                 __uint_as_float((unsigned)(a >> 32));
            }
#pragma unroll
        for (int off = 16; off >= 1; off >>= 1) {
            const bool up = (lane & off) != 0;
#pragma unroll
            for (int j = 0; j < off; ++j) {
                float keep = up ? cur[j + off] : cur[j];
                float give = up ? cur[j] : cur[j + off];
                keep += __shfl_xor_sync(0xffffffffu, give, off);
                cur[j] = keep;
            }
        }
        // lane holds partial of output value index `lane` (token lane>>3, out lane&7)
        bar_cons();                    // (A) warp0's read of previous red done
        red[wid * 32 + lane] = cur[0];
        bar_cons();                    // (B) red visible
        if (wid == 0) {
            float s = bval;
#pragma unroll
            for (int ww = 0; ww < 8; ++ww) s += red[ww * 32 + lane];
            out[(size_t)(s0 + k * grid) * 32 + lane] = s;
        }
    }
}

extern "C" void kernel_launch(void* const* d_in, const int* in_sizes, int n_in,
                              void* d_out, int out_size) {
    const int*   ids  = (const int*)  d_in[0];
    const float* M    = (const float*)d_in[1];
    const float* W    = (const float*)d_in[2];
    const float* bias = (const float*)d_in[3];
    float*       out  = (float*)d_out;

    cudaFuncSetAttribute(gather_proj_r4,
                         cudaFuncAttributeMaxDynamicSharedMemorySize, SM_TOT);

    int nsm = 148;
    cudaDeviceGetAttribute(&nsm, cudaDevAttrMultiProcessorCount, 0);

    gather_proj_r4<<<nsm, NTHR, SM_TOT>>>(ids, M, W, bias, out);
}